// round 13
// baseline (speedup 1.0000x reference)
#include <cuda_runtime.h>
#include <cstdint>

// Problem geometry (fixed for this dataset instance)
#define CC    3
#define HH    496
#define WW    432
#define HWSZ  (HH * WW)            // 214272
#define PLANE (CC * HWSZ)          // 642816
#define MAXB  8
#define NBUCK 8192                 // ordered_bits >> 19
#define NSH   4                    // histogram shards (contention relief)
#define CAP   4096                 // candidate buffer per batch
#define SURVCAP 131072             // survivor buffer per batch (expect ~72K)
#define K1_BLOCKS ((PLANE + 2047) / 2048)   // 314 blocks of 256 thr x 8 px
#define SKEYS 768                  // smem staging cap (theoretical max 512/tile)
#define K4_WPB 8                   // warps (candidates) per k4 block

// Scratch. All of it is zero at module load, and every kernel leaves its part
// zeroed for the next graph replay (self-cleaning) -> NO memset nodes.
#define HIST_INTS   (MAXB * NSH * NBUCK)       // 262144 ints = 1 MB
#define SCOUNT_OFF  (HIST_INTS)                // 8 ints
#define COUNT_OFF   (HIST_INTS + MAXB)         // 8 ints
#define ZERO_INTS   (HIST_INTS + 2 * MAXB)

__device__ int                g_zero[ZERO_INTS];
__device__ int                g_thresh[MAXB];
__device__ unsigned long long g_surv[MAXB * SURVCAP];   // 8 MB
__device__ unsigned long long g_cand[MAXB * CAP];

__device__ __forceinline__ float sigclip(float x) {
    float s = 1.0f / (1.0f + __expf(-x));
    return fminf(fmaxf(s, 1.0e-4f), 1.0f - 1.0e-4f);
}

// total-order key for floats (monotone map to uint32, ascending)
__device__ __forceinline__ unsigned int ordkey(float v) {
    unsigned int bits = __float_as_uint(v);
    return bits ^ ((unsigned int)((int)bits >> 31) | 0x80000000u);
}

// ---------------------------------------------------------------------------
// K1: raw-domain 3x3 NMS -> survivor list + sharded hist.
//     8 px/thread; warp-aggregated smem staging; coalesced flush.
//     Also zeroes count[b] (consumed by k3/k4 later this replay).
// ---------------------------------------------------------------------------
__global__ __launch_bounds__(256)
void k1_nms(const float* __restrict__ hm) {
    int b    = blockIdx.y;
    int base = blockIdx.x * 2048 + threadIdx.x * 8;   // within plane
    int sh   = threadIdx.x & (NSH - 1);
    int lane = threadIdx.x & 31;

    __shared__ int s_cnt, s_base;
    __shared__ unsigned long long s_keys[SKEYS];
    if (threadIdx.x == 0) {
        s_cnt = 0;
        if (blockIdx.x == 0) g_zero[COUNT_OFF + b] = 0;   // self-clean for k3
    }
    __syncthreads();

    float rc[10], ru[10], rd[10];
    bool active = (base < PLANE);

    if (active) {
        const float* plane = hm + (size_t)b * PLANE;
        int hw = base % HWSZ;
        int h  = hw / WW;
        int w  = hw % WW;
        const float* p = plane + base;
        const float NEG = -3.4e38f;

        {
            float4 a = *reinterpret_cast<const float4*>(p);
            float4 c = *reinterpret_cast<const float4*>(p + 4);
            rc[1]=a.x; rc[2]=a.y; rc[3]=a.z; rc[4]=a.w;
            rc[5]=c.x; rc[6]=c.y; rc[7]=c.z; rc[8]=c.w;
            rc[0] = (w > 0)      ? p[-1] : NEG;
            rc[9] = (w + 8 < WW) ? p[8]  : NEG;
        }
        if (h > 0) {
            const float* q = p - WW;
            float4 a = *reinterpret_cast<const float4*>(q);
            float4 c = *reinterpret_cast<const float4*>(q + 4);
            ru[1]=a.x; ru[2]=a.y; ru[3]=a.z; ru[4]=a.w;
            ru[5]=c.x; ru[6]=c.y; ru[7]=c.z; ru[8]=c.w;
            ru[0] = (w > 0)      ? q[-1] : NEG;
            ru[9] = (w + 8 < WW) ? q[8]  : NEG;
        } else {
            #pragma unroll
            for (int j = 0; j < 10; j++) ru[j] = NEG;
        }
        if (h + 1 < HH) {
            const float* q = p + WW;
            float4 a = *reinterpret_cast<const float4*>(q);
            float4 c = *reinterpret_cast<const float4*>(q + 4);
            rd[1]=a.x; rd[2]=a.y; rd[3]=a.z; rd[4]=a.w;
            rd[5]=c.x; rd[6]=c.y; rd[7]=c.z; rd[8]=c.w;
            rd[0] = (w > 0)      ? q[-1] : NEG;
            rd[9] = (w + 8 < WW) ? q[8]  : NEG;
        } else {
            #pragma unroll
            for (int j = 0; j < 10; j++) rd[j] = NEG;
        }
    }

    // Warp-aggregated survivor emission: one smem atomic per warp per j.
    #pragma unroll
    for (int j = 0; j < 8; j++) {
        bool keep = false;
        unsigned long long key = 0;
        if (active) {
            float v = rc[j + 1];
            float m = fmaxf(rc[j], rc[j + 2]);
            m = fmaxf(m, fmaxf(fmaxf(ru[j], ru[j + 1]), ru[j + 2]));
            m = fmaxf(m, fmaxf(fmaxf(rd[j], rd[j + 1]), rd[j + 2]));
            if (v >= m) {
                keep = true;
                unsigned int ord = ordkey(v);
                atomicAdd(&g_zero[(b * NSH + sh) * NBUCK + (int)(ord >> 19)], 1);
                unsigned int idx = (unsigned int)(base + j);   // c*HW + hw
                key = ((unsigned long long)ord << 32) |
                      (unsigned long long)(~idx);
            }
        }
        unsigned mask = __ballot_sync(0xFFFFFFFFu, keep);
        if (mask) {
            int leader = __ffs(mask) - 1;
            int wbase = 0;
            if (lane == leader) wbase = atomicAdd(&s_cnt, __popc(mask));
            wbase = __shfl_sync(0xFFFFFFFFu, wbase, leader);
            if (keep) {
                int pos = wbase + __popc(mask & ((1u << lane) - 1));
                if (pos < SKEYS) s_keys[pos] = key;
            }
        }
    }

    __syncthreads();
    if (threadIdx.x == 0)
        s_base = atomicAdd(&g_zero[SCOUNT_OFF + b], s_cnt);
    __syncthreads();

    int nblk  = (s_cnt < SKEYS) ? s_cnt : SKEYS;
    int gbase = s_base;
    for (int i = threadIdx.x; i < nblk; i += 256) {
        int pp = gbase + i;
        if (pp < SURVCAP) g_surv[b * SURVCAP + pp] = s_keys[i];
    }
}

// ---------------------------------------------------------------------------
// K2: per-batch threshold bucket via parallel suffix scan.
//     Zeroes the histogram words it consumed (self-clean for next replay).
// ---------------------------------------------------------------------------
__global__ void k2_thresh(int K) {
    int b = blockIdx.x;
    __shared__ int suf[256];
    __shared__ int merged[NBUCK];       // 32 KB: shard-summed histogram
    int t = threadIdx.x;                // 256 threads, 32 buckets each
    int s = 0;
    #pragma unroll 1
    for (int j = 0; j < 32; j++) {
        int bk = t * 32 + j;
        int v = 0;
        #pragma unroll
        for (int sh = 0; sh < NSH; sh++) {
            int* hp = &g_zero[(b * NSH + sh) * NBUCK + bk];
            v += *hp;
            *hp = 0;                    // self-clean
        }
        merged[bk] = v;
        s += v;
    }
    suf[t] = s;
    __syncthreads();

    // Hillis-Steele inclusive suffix sum over 256 chunks
    #pragma unroll
    for (int off = 1; off < 256; off <<= 1) {
        int v = (t + off < 256) ? suf[t + off] : 0;
        __syncthreads();
        suf[t] += v;
        __syncthreads();
    }

    if (t == 0 && suf[0] < K) g_thresh[b] = 0;   // fewer than K total
    int snext = (t < 255) ? suf[t + 1] : 0;
    if (suf[t] >= K && snext < K) {
        int cum = snext;
        int T = t * 32;
        for (int j = 31; j >= 0; j--) {
            cum += merged[t * 32 + j];
            if (cum >= K) { T = t * 32 + j; break; }
        }
        g_thresh[b] = T;   // collect criterion: bucket >= T
    }
}

// ---------------------------------------------------------------------------
// K3: filter survivor list by threshold bucket into candidate arrays
// ---------------------------------------------------------------------------
__global__ __launch_bounds__(256)
void k3_collect() {
    int b    = blockIdx.y;
    int base = (blockIdx.x * 256 + threadIdx.x) * 4;
    int n = g_zero[SCOUNT_OFF + b];
    if (n > SURVCAP) n = SURVCAP;
    if (base >= n) return;
    int T = g_thresh[b];

    const ulonglong2* sp =
        reinterpret_cast<const ulonglong2*>(&g_surv[b * SURVCAP + base]);
    ulonglong2 v0 = sp[0];
    ulonglong2 v1 = sp[1];
    unsigned long long kk[4] = { v0.x, v0.y, v1.x, v1.y };

    #pragma unroll
    for (int j = 0; j < 4; j++) {
        if (base + j >= n) break;
        unsigned long long key = kk[j];
        if ((int)(key >> 51) >= T) {
            int pos = atomicAdd(&g_zero[COUNT_OFF + b], 1);
            if (pos < CAP) g_cand[b * CAP + pos] = key;
        }
    }
}

// ---------------------------------------------------------------------------
// K4: warp-per-candidate rank selection, direct global reads (L2-resident).
//     Zeroes scount[b] (self-clean) and zero-fills output rows [n, K).
// ---------------------------------------------------------------------------
__global__ __launch_bounds__(32 * K4_WPB)
void k4_rank_gather(const float* __restrict__ cen_offset,
                    const float* __restrict__ direction,
                    const float* __restrict__ z_coor,
                    const float* __restrict__ dimf,
                    float* __restrict__ out,
                    int K) {
    int b    = blockIdx.y;
    int lane = threadIdx.x & 31;
    int cand = blockIdx.x * K4_WPB + (threadIdx.x >> 5);

    if (blockIdx.x == 0 && threadIdx.x == 0)
        g_zero[SCOUNT_OFF + b] = 0;          // self-clean (k3 already consumed)

    int n = g_zero[COUNT_OFF + b];
    if (n > CAP) n = CAP;

    if (cand >= n) {
        // rows [n, K) have no candidate: zero-fill
        if (cand < K && lane == 0) {
            float* o = out + ((size_t)b * K + cand) * 10;
            #pragma unroll
            for (int q = 0; q < 10; q++) o[q] = 0.0f;
        }
        return;
    }

    const unsigned long long* cp = &g_cand[b * CAP];
    unsigned long long key = cp[cand];

    int rank = 0;
    for (int j = lane; j < n; j += 32)
        rank += (cp[j] > key);
    rank = __reduce_add_sync(0xFFFFFFFFu, rank);
    if (rank >= K) return;

    if (lane == 0) {
        unsigned int ord  = (unsigned int)(key >> 32);
        unsigned int bits = (ord & 0x80000000u) ? (ord ^ 0x80000000u) : ~ord;
        float score = sigclip(__uint_as_float(bits));
        unsigned int idx = ~((unsigned int)key);       // c*HW + hw
        int c  = (int)(idx / HWSZ);
        int hw = (int)(idx - (unsigned int)c * HWSZ);
        int r  = hw / WW;
        int w  = hw - r * WW;

        const float* off = cen_offset + (size_t)b * 2 * HWSZ;
        const float* dir = direction  + (size_t)b * 2 * HWSZ;
        const float* zc  = z_coor     + (size_t)b * 1 * HWSZ;
        const float* dm  = dimf       + (size_t)b * 3 * HWSZ;

        float* o = out + ((size_t)b * K + rank) * 10;
        o[0] = score;
        o[1] = (float)w + sigclip(off[hw]);
        o[2] = (float)r + sigclip(off[HWSZ + hw]);
        o[3] = zc[hw];
        o[4] = dm[hw];
        o[5] = dm[HWSZ + hw];
        o[6] = dm[2 * HWSZ + hw];
        o[7] = dir[hw];
        o[8] = dir[HWSZ + hw];
        o[9] = (float)c;
    }
}

// ---------------------------------------------------------------------------
// Host launcher — exactly 4 graph nodes, no memsets (state is self-cleaning;
// __device__ globals are zero-initialized at module load for the first run).
// ---------------------------------------------------------------------------
extern "C" void kernel_launch(void* const* d_in, const int* in_sizes, int n_in,
                              void* d_out, int out_size) {
    const float* hm   = (const float*)d_in[0];
    const float* off  = (const float*)d_in[1];
    const float* dir  = (const float*)d_in[2];
    const float* zc   = (const float*)d_in[3];
    const float* dm   = (const float*)d_in[4];
    float* out = (float*)d_out;

    int B = in_sizes[0] / PLANE;
    if (B < 1) B = 1;
    if (B > MAXB) B = MAXB;
    int K = out_size / (B * 10);
    if (K < 1) K = 1;

    k1_nms<<<dim3(K1_BLOCKS, B), 256>>>(hm);
    k2_thresh<<<B, 256>>>(K);
    k3_collect<<<dim3(SURVCAP / 1024, B), 256>>>();
    k4_rank_gather<<<dim3(CAP / K4_WPB, B), 32 * K4_WPB>>>(off, dir, zc, dm, out, K);
}

// round 14
// speedup vs baseline: 2.2255x; 2.2255x over previous
#include <cuda_runtime.h>
#include <cstdint>

// Problem geometry (fixed for this dataset instance)
#define CC    3
#define HH    496
#define WW    432
#define HWSZ  (HH * WW)            // 214272
#define PLANE (CC * HWSZ)          // 642816
#define MAXB  8
#define NBUCK 8192                 // ordered_bits >> 19
#define NSH   4                    // histogram shards (contention relief)
#define CAP   4096                 // candidate buffer per batch
#define SURVCAP 131072             // survivor buffer per batch (expect ~72K)
#define K1_BLOCKS ((PLANE + 2047) / 2048)   // 314 blocks of 256 thr x 8 px
#define SKEYS 768                  // smem staging cap (theoretical max 512/tile)
#define K4_WPB 8                   // warps (candidates) per k4 block

// One contiguous zeroed scratch region: hist[b][sh][bucket] then counters.
#define HIST_INTS   (MAXB * NSH * NBUCK)       // 262144 ints = 1 MB
#define SCOUNT_OFF  (HIST_INTS)                // 8 ints
#define COUNT_OFF   (HIST_INTS + MAXB)         // 8 ints
#define ZERO_INTS   (HIST_INTS + 2 * MAXB)

__device__ int                g_zero[ZERO_INTS];
__device__ int                g_thresh[MAXB];
__device__ unsigned long long g_surv[MAXB * SURVCAP];   // 8 MB
__device__ unsigned long long g_cand[MAXB * CAP];

__device__ __forceinline__ float sigclip(float x) {
    float s = 1.0f / (1.0f + __expf(-x));
    return fminf(fmaxf(s, 1.0e-4f), 1.0f - 1.0e-4f);
}

// total-order key for floats (monotone map to uint32, ascending)
__device__ __forceinline__ unsigned int ordkey(float v) {
    unsigned int bits = __float_as_uint(v);
    return bits ^ ((unsigned int)((int)bits >> 31) | 0x80000000u);
}

// ---------------------------------------------------------------------------
// K0: zero scratch + output (replaces both memset nodes; also makes the
//     launch stream kernels-only so ncu's launch accounting sees every phase)
// ---------------------------------------------------------------------------
__global__ __launch_bounds__(1024)
void k0_zero(float* __restrict__ out, int out_n) {
    int i = blockIdx.x * 1024 + threadIdx.x;
    if (i < ZERO_INTS) g_zero[i] = 0;
    int j = i - ZERO_INTS;
    if (j >= 0 && j < out_n) out[j] = 0.0f;
}

// ---------------------------------------------------------------------------
// K1: raw-domain 3x3 NMS -> survivor list + sharded hist.
//     8 px/thread; warp-aggregated smem staging; coalesced flush.
//     (byte-identical to the 80us best)
// ---------------------------------------------------------------------------
__global__ __launch_bounds__(256)
void k1_nms(const float* __restrict__ hm) {
    int b    = blockIdx.y;
    int base = blockIdx.x * 2048 + threadIdx.x * 8;   // within plane
    int sh   = threadIdx.x & (NSH - 1);
    int lane = threadIdx.x & 31;

    __shared__ int s_cnt, s_base;
    __shared__ unsigned long long s_keys[SKEYS];
    if (threadIdx.x == 0) s_cnt = 0;
    __syncthreads();

    float rc[10], ru[10], rd[10];
    bool active = (base < PLANE);

    if (active) {
        const float* plane = hm + (size_t)b * PLANE;
        int hw = base % HWSZ;
        int h  = hw / WW;
        int w  = hw % WW;
        const float* p = plane + base;
        const float NEG = -3.4e38f;

        {
            float4 a = *reinterpret_cast<const float4*>(p);
            float4 c = *reinterpret_cast<const float4*>(p + 4);
            rc[1]=a.x; rc[2]=a.y; rc[3]=a.z; rc[4]=a.w;
            rc[5]=c.x; rc[6]=c.y; rc[7]=c.z; rc[8]=c.w;
            rc[0] = (w > 0)      ? p[-1] : NEG;
            rc[9] = (w + 8 < WW) ? p[8]  : NEG;
        }
        if (h > 0) {
            const float* q = p - WW;
            float4 a = *reinterpret_cast<const float4*>(q);
            float4 c = *reinterpret_cast<const float4*>(q + 4);
            ru[1]=a.x; ru[2]=a.y; ru[3]=a.z; ru[4]=a.w;
            ru[5]=c.x; ru[6]=c.y; ru[7]=c.z; ru[8]=c.w;
            ru[0] = (w > 0)      ? q[-1] : NEG;
            ru[9] = (w + 8 < WW) ? q[8]  : NEG;
        } else {
            #pragma unroll
            for (int j = 0; j < 10; j++) ru[j] = NEG;
        }
        if (h + 1 < HH) {
            const float* q = p + WW;
            float4 a = *reinterpret_cast<const float4*>(q);
            float4 c = *reinterpret_cast<const float4*>(q + 4);
            rd[1]=a.x; rd[2]=a.y; rd[3]=a.z; rd[4]=a.w;
            rd[5]=c.x; rd[6]=c.y; rd[7]=c.z; rd[8]=c.w;
            rd[0] = (w > 0)      ? q[-1] : NEG;
            rd[9] = (w + 8 < WW) ? q[8]  : NEG;
        } else {
            #pragma unroll
            for (int j = 0; j < 10; j++) rd[j] = NEG;
        }
    }

    // Warp-aggregated survivor emission: one smem atomic per warp per j.
    #pragma unroll
    for (int j = 0; j < 8; j++) {
        bool keep = false;
        unsigned long long key = 0;
        if (active) {
            float v = rc[j + 1];
            float m = fmaxf(rc[j], rc[j + 2]);
            m = fmaxf(m, fmaxf(fmaxf(ru[j], ru[j + 1]), ru[j + 2]));
            m = fmaxf(m, fmaxf(fmaxf(rd[j], rd[j + 1]), rd[j + 2]));
            if (v >= m) {
                keep = true;
                unsigned int ord = ordkey(v);
                atomicAdd(&g_zero[(b * NSH + sh) * NBUCK + (int)(ord >> 19)], 1);
                unsigned int idx = (unsigned int)(base + j);   // c*HW + hw
                key = ((unsigned long long)ord << 32) |
                      (unsigned long long)(~idx);
            }
        }
        unsigned mask = __ballot_sync(0xFFFFFFFFu, keep);
        if (mask) {
            int leader = __ffs(mask) - 1;
            int wbase = 0;
            if (lane == leader) wbase = atomicAdd(&s_cnt, __popc(mask));
            wbase = __shfl_sync(0xFFFFFFFFu, wbase, leader);
            if (keep) {
                int pos = wbase + __popc(mask & ((1u << lane) - 1));
                if (pos < SKEYS) s_keys[pos] = key;
            }
        }
    }

    __syncthreads();
    if (threadIdx.x == 0)
        s_base = atomicAdd(&g_zero[SCOUNT_OFF + b], s_cnt);
    __syncthreads();

    int nblk  = (s_cnt < SKEYS) ? s_cnt : SKEYS;
    int gbase = s_base;
    for (int i = threadIdx.x; i < nblk; i += 256) {
        int pp = gbase + i;
        if (pp < SURVCAP) g_surv[b * SURVCAP + pp] = s_keys[i];
    }
}

// ---------------------------------------------------------------------------
// K2: per-batch threshold bucket via parallel suffix scan.
//     1024 threads: 8 buckets/thread -> 4x the load MLP of the 256-thr version.
// ---------------------------------------------------------------------------
__global__ __launch_bounds__(1024)
void k2_thresh(int K) {
    int b = blockIdx.x;
    __shared__ int suf[1024];
    __shared__ int merged[NBUCK];       // 32 KB: shard-summed histogram
    int t = threadIdx.x;                // 1024 threads, 8 buckets each
    int s = 0;
    #pragma unroll 1
    for (int j = 0; j < 8; j++) {
        int bk = t * 8 + j;
        int v = 0;
        #pragma unroll
        for (int sh = 0; sh < NSH; sh++)
            v += g_zero[(b * NSH + sh) * NBUCK + bk];
        merged[bk] = v;
        s += v;
    }
    suf[t] = s;
    __syncthreads();

    // Hillis-Steele inclusive suffix sum over 1024 chunks
    #pragma unroll
    for (int off = 1; off < 1024; off <<= 1) {
        int v = (t + off < 1024) ? suf[t + off] : 0;
        __syncthreads();
        suf[t] += v;
        __syncthreads();
    }

    if (t == 0 && suf[0] < K) g_thresh[b] = 0;   // fewer than K total
    int snext = (t < 1023) ? suf[t + 1] : 0;
    if (suf[t] >= K && snext < K) {
        int cum = snext;
        int T = t * 8;
        for (int j = 7; j >= 0; j--) {
            cum += merged[t * 8 + j];
            if (cum >= K) { T = t * 8 + j; break; }
        }
        g_thresh[b] = T;   // collect criterion: bucket >= T
    }
}

// ---------------------------------------------------------------------------
// K3: filter survivor list by threshold bucket into candidate arrays
// ---------------------------------------------------------------------------
__global__ __launch_bounds__(256)
void k3_collect() {
    int b    = blockIdx.y;
    int base = (blockIdx.x * 256 + threadIdx.x) * 4;
    int n = g_zero[SCOUNT_OFF + b];
    if (n > SURVCAP) n = SURVCAP;
    if (base >= n) return;
    int T = g_thresh[b];

    const ulonglong2* sp =
        reinterpret_cast<const ulonglong2*>(&g_surv[b * SURVCAP + base]);
    ulonglong2 v0 = sp[0];
    ulonglong2 v1 = sp[1];
    unsigned long long kk[4] = { v0.x, v0.y, v1.x, v1.y };

    #pragma unroll
    for (int j = 0; j < 4; j++) {
        if (base + j >= n) break;
        unsigned long long key = kk[j];
        if ((int)(key >> 51) >= T) {
            int pos = atomicAdd(&g_zero[COUNT_OFF + b], 1);
            if (pos < CAP) g_cand[b * CAP + pos] = key;
        }
    }
}

// ---------------------------------------------------------------------------
// K4: warp-per-candidate rank selection, direct global reads (L2-resident).
// ---------------------------------------------------------------------------
__global__ __launch_bounds__(32 * K4_WPB)
void k4_rank_gather(const float* __restrict__ cen_offset,
                    const float* __restrict__ direction,
                    const float* __restrict__ z_coor,
                    const float* __restrict__ dimf,
                    float* __restrict__ out,
                    int K) {
    int b    = blockIdx.y;
    int lane = threadIdx.x & 31;
    int cand = blockIdx.x * K4_WPB + (threadIdx.x >> 5);
    int n    = g_zero[COUNT_OFF + b];
    if (n > CAP) n = CAP;
    if (cand >= n) return;

    const unsigned long long* cp = &g_cand[b * CAP];
    unsigned long long key = cp[cand];

    int rank = 0;
    for (int j = lane; j < n; j += 32)
        rank += (cp[j] > key);
    rank = __reduce_add_sync(0xFFFFFFFFu, rank);
    if (rank >= K) return;

    if (lane == 0) {
        unsigned int ord  = (unsigned int)(key >> 32);
        unsigned int bits = (ord & 0x80000000u) ? (ord ^ 0x80000000u) : ~ord;
        float score = sigclip(__uint_as_float(bits));
        unsigned int idx = ~((unsigned int)key);       // c*HW + hw
        int c  = (int)(idx / HWSZ);
        int hw = (int)(idx - (unsigned int)c * HWSZ);
        int r  = hw / WW;
        int w  = hw - r * WW;

        const float* off = cen_offset + (size_t)b * 2 * HWSZ;
        const float* dir = direction  + (size_t)b * 2 * HWSZ;
        const float* zc  = z_coor     + (size_t)b * 1 * HWSZ;
        const float* dm  = dimf       + (size_t)b * 3 * HWSZ;

        float* o = out + ((size_t)b * K + rank) * 10;
        o[0] = score;
        o[1] = (float)w + sigclip(off[hw]);
        o[2] = (float)r + sigclip(off[HWSZ + hw]);
        o[3] = zc[hw];
        o[4] = dm[hw];
        o[5] = dm[HWSZ + hw];
        o[6] = dm[2 * HWSZ + hw];
        o[7] = dir[hw];
        o[8] = dir[HWSZ + hw];
        o[9] = (float)c;
    }
}

// ---------------------------------------------------------------------------
// Host launcher — kernels only (k0 replaces both memsets).
// ---------------------------------------------------------------------------
extern "C" void kernel_launch(void* const* d_in, const int* in_sizes, int n_in,
                              void* d_out, int out_size) {
    const float* hm   = (const float*)d_in[0];
    const float* off  = (const float*)d_in[1];
    const float* dir  = (const float*)d_in[2];
    const float* zc   = (const float*)d_in[3];
    const float* dm   = (const float*)d_in[4];
    float* out = (float*)d_out;

    int B = in_sizes[0] / PLANE;
    if (B < 1) B = 1;
    if (B > MAXB) B = MAXB;
    int K = out_size / (B * 10);
    if (K < 1) K = 1;

    int ztotal = ZERO_INTS + out_size;
    k0_zero<<<(ztotal + 1023) / 1024, 1024>>>(out, out_size);
    k1_nms<<<dim3(K1_BLOCKS, B), 256>>>(hm);
    k2_thresh<<<B, 1024>>>(K);
    k3_collect<<<dim3(SURVCAP / 1024, B), 256>>>();
    k4_rank_gather<<<dim3(CAP / K4_WPB, B), 32 * K4_WPB>>>(off, dir, zc, dm, out, K);
}

// round 15
// speedup vs baseline: 2.3003x; 1.0336x over previous
#include <cuda_runtime.h>
#include <cstdint>

// Problem geometry (fixed for this dataset instance)
#define CC    3
#define HH    496
#define WW    432
#define HWSZ  (HH * WW)            // 214272
#define PLANE (CC * HWSZ)          // 642816
#define MAXB  8
#define NBUCK 8192                 // ordered_bits >> 19
#define NSH   4                    // histogram shards (contention relief)
#define CAP   4096                 // candidate buffer per batch
#define SURVCAP 131072             // survivor buffer per batch (expect ~72K)
#define K1_BLOCKS ((PLANE + 2047) / 2048)   // 314 blocks of 256 thr x 8 px
#define SKEYS 768                  // smem staging cap (theoretical max 512/tile)
#define K4_BLK 64                  // blocks per batch in k4 (8 warps each)

// One contiguous zeroed scratch region: hist[b][sh][bucket] then counters.
#define HIST_INTS   (MAXB * NSH * NBUCK)       // 262144 ints = 1 MB
#define SCOUNT_OFF  (HIST_INTS)                // 8 ints
#define COUNT_OFF   (HIST_INTS + MAXB)         // 8 ints
#define ZERO_INTS   (HIST_INTS + 2 * MAXB)

__device__ int                g_zero[ZERO_INTS];
__device__ int                g_thresh[MAXB];
__device__ unsigned long long g_surv[MAXB * SURVCAP];   // 8 MB
__device__ unsigned long long g_cand[MAXB * CAP];

__device__ __forceinline__ float sigclip(float x) {
    float s = 1.0f / (1.0f + __expf(-x));
    return fminf(fmaxf(s, 1.0e-4f), 1.0f - 1.0e-4f);
}

// total-order key for floats (monotone map to uint32, ascending)
__device__ __forceinline__ unsigned int ordkey(float v) {
    unsigned int bits = __float_as_uint(v);
    return bits ^ ((unsigned int)((int)bits >> 31) | 0x80000000u);
}

// ---------------------------------------------------------------------------
// K0: zero scratch + output (kernel node, NOT a memset node — memset nodes
//     measured ~12us each in this graph)
// ---------------------------------------------------------------------------
__global__ __launch_bounds__(1024)
void k0_zero(float* __restrict__ out, int out_n) {
    int i = blockIdx.x * 1024 + threadIdx.x;
    if (i < ZERO_INTS) g_zero[i] = 0;
    int j = i - ZERO_INTS;
    if (j >= 0 && j < out_n) out[j] = 0.0f;
}

// ---------------------------------------------------------------------------
// K1: raw-domain 3x3 NMS -> survivor list + sharded hist.
//     8 px/thread; warp-aggregated smem staging; coalesced flush.
//     (byte-identical to the 55us best)
// ---------------------------------------------------------------------------
__global__ __launch_bounds__(256)
void k1_nms(const float* __restrict__ hm) {
    int b    = blockIdx.y;
    int base = blockIdx.x * 2048 + threadIdx.x * 8;   // within plane
    int sh   = threadIdx.x & (NSH - 1);
    int lane = threadIdx.x & 31;

    __shared__ int s_cnt, s_base;
    __shared__ unsigned long long s_keys[SKEYS];
    if (threadIdx.x == 0) s_cnt = 0;
    __syncthreads();

    float rc[10], ru[10], rd[10];
    bool active = (base < PLANE);

    if (active) {
        const float* plane = hm + (size_t)b * PLANE;
        int hw = base % HWSZ;
        int h  = hw / WW;
        int w  = hw % WW;
        const float* p = plane + base;
        const float NEG = -3.4e38f;

        {
            float4 a = *reinterpret_cast<const float4*>(p);
            float4 c = *reinterpret_cast<const float4*>(p + 4);
            rc[1]=a.x; rc[2]=a.y; rc[3]=a.z; rc[4]=a.w;
            rc[5]=c.x; rc[6]=c.y; rc[7]=c.z; rc[8]=c.w;
            rc[0] = (w > 0)      ? p[-1] : NEG;
            rc[9] = (w + 8 < WW) ? p[8]  : NEG;
        }
        if (h > 0) {
            const float* q = p - WW;
            float4 a = *reinterpret_cast<const float4*>(q);
            float4 c = *reinterpret_cast<const float4*>(q + 4);
            ru[1]=a.x; ru[2]=a.y; ru[3]=a.z; ru[4]=a.w;
            ru[5]=c.x; ru[6]=c.y; ru[7]=c.z; ru[8]=c.w;
            ru[0] = (w > 0)      ? q[-1] : NEG;
            ru[9] = (w + 8 < WW) ? q[8]  : NEG;
        } else {
            #pragma unroll
            for (int j = 0; j < 10; j++) ru[j] = NEG;
        }
        if (h + 1 < HH) {
            const float* q = p + WW;
            float4 a = *reinterpret_cast<const float4*>(q);
            float4 c = *reinterpret_cast<const float4*>(q + 4);
            rd[1]=a.x; rd[2]=a.y; rd[3]=a.z; rd[4]=a.w;
            rd[5]=c.x; rd[6]=c.y; rd[7]=c.z; rd[8]=c.w;
            rd[0] = (w > 0)      ? q[-1] : NEG;
            rd[9] = (w + 8 < WW) ? q[8]  : NEG;
        } else {
            #pragma unroll
            for (int j = 0; j < 10; j++) rd[j] = NEG;
        }
    }

    // Warp-aggregated survivor emission: one smem atomic per warp per j.
    #pragma unroll
    for (int j = 0; j < 8; j++) {
        bool keep = false;
        unsigned long long key = 0;
        if (active) {
            float v = rc[j + 1];
            float m = fmaxf(rc[j], rc[j + 2]);
            m = fmaxf(m, fmaxf(fmaxf(ru[j], ru[j + 1]), ru[j + 2]));
            m = fmaxf(m, fmaxf(fmaxf(rd[j], rd[j + 1]), rd[j + 2]));
            if (v >= m) {
                keep = true;
                unsigned int ord = ordkey(v);
                atomicAdd(&g_zero[(b * NSH + sh) * NBUCK + (int)(ord >> 19)], 1);
                unsigned int idx = (unsigned int)(base + j);   // c*HW + hw
                key = ((unsigned long long)ord << 32) |
                      (unsigned long long)(~idx);
            }
        }
        unsigned mask = __ballot_sync(0xFFFFFFFFu, keep);
        if (mask) {
            int leader = __ffs(mask) - 1;
            int wbase = 0;
            if (lane == leader) wbase = atomicAdd(&s_cnt, __popc(mask));
            wbase = __shfl_sync(0xFFFFFFFFu, wbase, leader);
            if (keep) {
                int pos = wbase + __popc(mask & ((1u << lane) - 1));
                if (pos < SKEYS) s_keys[pos] = key;
            }
        }
    }

    __syncthreads();
    if (threadIdx.x == 0)
        s_base = atomicAdd(&g_zero[SCOUNT_OFF + b], s_cnt);
    __syncthreads();

    int nblk  = (s_cnt < SKEYS) ? s_cnt : SKEYS;
    int gbase = s_base;
    for (int i = threadIdx.x; i < nblk; i += 256) {
        int pp = gbase + i;
        if (pp < SURVCAP) g_surv[b * SURVCAP + pp] = s_keys[i];
    }
}

// ---------------------------------------------------------------------------
// K2: threshold select — register buckets + warp-shuffle suffix scan.
//     1024 threads x 8 buckets; 32 fully-unrolled loads (MLP=32); 2 barriers.
// ---------------------------------------------------------------------------
__global__ __launch_bounds__(1024)
void k2_thresh(int K) {
    int b    = blockIdx.x;
    int t    = threadIdx.x;
    int lane = t & 31;
    int wid  = t >> 5;

    __shared__ int warpsum[32];
    __shared__ int wsuf[32];

    int bk[8];
    int s = 0;
    #pragma unroll
    for (int j = 0; j < 8; j++) {
        int bkix = t * 8 + j;
        int v = 0;
        #pragma unroll
        for (int sh = 0; sh < NSH; sh++)
            v += g_zero[(b * NSH + sh) * NBUCK + bkix];
        bk[j] = v;
        s += v;
    }

    // within-warp inclusive suffix sum (lane..31)
    int val = s;
    #pragma unroll
    for (int d = 1; d < 32; d <<= 1) {
        int v = __shfl_down_sync(0xFFFFFFFFu, val, d);
        if (lane + d < 32) val += v;
    }
    if (lane == 0) warpsum[wid] = val;
    __syncthreads();

    if (wid == 0) {
        int wv = warpsum[lane];
        #pragma unroll
        for (int d = 1; d < 32; d <<= 1) {
            int v = __shfl_down_sync(0xFFFFFFFFu, wv, d);
            if (lane + d < 32) wv += v;
        }
        wsuf[lane] = wv;     // inclusive suffix over warp totals
    }
    __syncthreads();

    int higher = (wid < 31) ? wsuf[wid + 1] : 0;
    int suf    = val + higher;        // inclusive suffix sum at thread t
    int snext  = suf - s;             // exclusive (suffix at t+1 boundary)

    if (t == 0 && wsuf[0] < K) g_thresh[b] = 0;      // fewer than K total
    if (suf >= K && snext < K) {
        int cum = snext;
        int T = t * 8;
        #pragma unroll
        for (int j = 7; j >= 0; j--) {
            cum += bk[j];
            if (cum >= K) { T = t * 8 + j; break; }
        }
        g_thresh[b] = T;   // collect criterion: bucket >= T
    }
}

// ---------------------------------------------------------------------------
// K3: filter survivors -> candidates. 8 keys/thread, column-strided
//     (fully coalesced LDG.64 x8, MLP=8). 64 blocks per batch.
// ---------------------------------------------------------------------------
__global__ __launch_bounds__(256)
void k3_collect() {
    int b   = blockIdx.y;
    int tid = threadIdx.x;
    int n = g_zero[SCOUNT_OFF + b];
    if (n > SURVCAP) n = SURVCAP;
    int bbase = blockIdx.x * 2048;
    if (bbase >= n) return;
    int T = g_thresh[b];

    const unsigned long long* sp = &g_surv[b * SURVCAP + bbase];
    unsigned long long kk[8];
    #pragma unroll
    for (int j = 0; j < 8; j++)
        kk[j] = sp[tid + j * 256];          // may be stale past n; guarded below

    #pragma unroll
    for (int j = 0; j < 8; j++) {
        int idx = bbase + tid + j * 256;
        if (idx < n && (int)(kk[j] >> 51) >= T) {
            int pos = atomicAdd(&g_zero[COUNT_OFF + b], 1);
            if (pos < CAP) g_cand[b * CAP + pos] = kk[j];
        }
    }
}

// ---------------------------------------------------------------------------
// K4: warp-per-candidate rank selection with candidate-stride loop.
//     64 blocks x 8 warps per batch; covers up to CAP candidates.
// ---------------------------------------------------------------------------
__global__ __launch_bounds__(256)
void k4_rank_gather(const float* __restrict__ cen_offset,
                    const float* __restrict__ direction,
                    const float* __restrict__ z_coor,
                    const float* __restrict__ dimf,
                    float* __restrict__ out,
                    int K) {
    int b    = blockIdx.y;
    int lane = threadIdx.x & 31;
    int warp = threadIdx.x >> 5;
    int n    = g_zero[COUNT_OFF + b];
    if (n > CAP) n = CAP;

    const unsigned long long* cp = &g_cand[b * CAP];
    const float* off = cen_offset + (size_t)b * 2 * HWSZ;
    const float* dir = direction  + (size_t)b * 2 * HWSZ;
    const float* zc  = z_coor     + (size_t)b * 1 * HWSZ;
    const float* dm  = dimf       + (size_t)b * 3 * HWSZ;

    for (int cand = blockIdx.x * 8 + warp; cand < n; cand += K4_BLK * 8) {
        unsigned long long key = cp[cand];

        int rank = 0;
        for (int j = lane; j < n; j += 32)
            rank += (cp[j] > key);
        rank = __reduce_add_sync(0xFFFFFFFFu, rank);
        if (rank >= K) continue;

        if (lane == 0) {
            unsigned int ord  = (unsigned int)(key >> 32);
            unsigned int bits = (ord & 0x80000000u) ? (ord ^ 0x80000000u) : ~ord;
            float score = sigclip(__uint_as_float(bits));
            unsigned int idx = ~((unsigned int)key);       // c*HW + hw
            int c  = (int)(idx / HWSZ);
            int hw = (int)(idx - (unsigned int)c * HWSZ);
            int r  = hw / WW;
            int w  = hw - r * WW;

            float* o = out + ((size_t)b * K + rank) * 10;
            o[0] = score;
            o[1] = (float)w + sigclip(off[hw]);
            o[2] = (float)r + sigclip(off[HWSZ + hw]);
            o[3] = zc[hw];
            o[4] = dm[hw];
            o[5] = dm[HWSZ + hw];
            o[6] = dm[2 * HWSZ + hw];
            o[7] = dir[hw];
            o[8] = dir[HWSZ + hw];
            o[9] = (float)c;
        }
    }
}

// ---------------------------------------------------------------------------
// Host launcher — kernel nodes only.
// ---------------------------------------------------------------------------
extern "C" void kernel_launch(void* const* d_in, const int* in_sizes, int n_in,
                              void* d_out, int out_size) {
    const float* hm   = (const float*)d_in[0];
    const float* off  = (const float*)d_in[1];
    const float* dir  = (const float*)d_in[2];
    const float* zc   = (const float*)d_in[3];
    const float* dm   = (const float*)d_in[4];
    float* out = (float*)d_out;

    int B = in_sizes[0] / PLANE;
    if (B < 1) B = 1;
    if (B > MAXB) B = MAXB;
    int K = out_size / (B * 10);
    if (K < 1) K = 1;

    int ztotal = ZERO_INTS + out_size;
    k0_zero<<<(ztotal + 1023) / 1024, 1024>>>(out, out_size);
    k1_nms<<<dim3(K1_BLOCKS, B), 256>>>(hm);
    k2_thresh<<<B, 1024>>>(K);
    k3_collect<<<dim3(SURVCAP / 2048, B), 256>>>();
    k4_rank_gather<<<dim3(K4_BLK, B), 256>>>(off, dir, zc, dm, out, K);
}

// round 17
// speedup vs baseline: 2.4902x; 1.0826x over previous
#include <cuda_runtime.h>
#include <cstdint>

// Problem geometry (fixed for this dataset instance)
#define CC    3
#define HH    496
#define WW    432
#define HWSZ  (HH * WW)            // 214272
#define PLANE (CC * HWSZ)          // 642816
#define MAXB  8
#define NBUCK 8192                 // ordered_bits >> 19
#define NSH   4                    // histogram shards (contention relief)
#define CAP   4096                 // candidate buffer per batch
#define HICAP 16384                // stored (high) survivors per batch
#define K1_BLOCKS ((PLANE + 2047) / 2048)   // 314 blocks of 256 thr x 8 px
#define SKEYS 768                  // smem staging cap per k1 block
#define K4_BLK 64                  // blocks per batch in k4 (8 warps each)

// Cutoff: store survivors with raw v >= 2.5 (bucket >= CUTB). Threshold for
// this input is ~3.16, so the high list always suffices; k3b covers the rest.
#define CUTRAW 2.5f
#define CUTB   6148                // ordkey(2.5f) >> 19

// One contiguous zeroed scratch region: hist[b][sh][bucket] then counters.
#define HIST_INTS   (MAXB * NSH * NBUCK)       // 262144 ints = 1 MB
#define SCOUNT_OFF  (HIST_INTS)                // 8 ints (high-survivor counts)
#define COUNT_OFF   (HIST_INTS + MAXB)         // 8 ints (candidate counts)
#define ZERO_INTS   (HIST_INTS + 2 * MAXB)

__device__ int                g_zero[ZERO_INTS];
__device__ int                g_thresh[MAXB];
__device__ unsigned long long g_surv[MAXB * HICAP];     // 1 MB (high keys)
__device__ unsigned long long g_cand[MAXB * CAP];

__device__ __forceinline__ float sigclip(float x) {
    float s = 1.0f / (1.0f + __expf(-x));
    return fminf(fmaxf(s, 1.0e-4f), 1.0f - 1.0e-4f);
}

// total-order key for floats (monotone map to uint32, ascending)
__device__ __forceinline__ unsigned int ordkey(float v) {
    unsigned int bits = __float_as_uint(v);
    return bits ^ ((unsigned int)((int)bits >> 31) | 0x80000000u);
}

// ---------------------------------------------------------------------------
// K0: zero scratch + output (kernel node; memset nodes cost ~12us each here)
// ---------------------------------------------------------------------------
__global__ __launch_bounds__(1024)
void k0_zero(float* __restrict__ out, int out_n) {
    int i = blockIdx.x * 1024 + threadIdx.x;
    if (i < ZERO_INTS) g_zero[i] = 0;
    int j = i - ZERO_INTS;
    if (j >= 0 && j < out_n) out[j] = 0.0f;
}

// ---------------------------------------------------------------------------
// K1: raw-domain 3x3 NMS. Histogram ALL survivors (exact threshold);
//     STORE only high survivors (v >= CUTRAW) via warp-aggregated staging.
// ---------------------------------------------------------------------------
__global__ __launch_bounds__(256)
void k1_nms(const float* __restrict__ hm) {
    int b    = blockIdx.y;
    int base = blockIdx.x * 2048 + threadIdx.x * 8;   // within plane
    int sh   = threadIdx.x & (NSH - 1);
    int lane = threadIdx.x & 31;

    __shared__ int s_cnt, s_base;
    __shared__ unsigned long long s_keys[SKEYS];
    if (threadIdx.x == 0) s_cnt = 0;
    __syncthreads();

    float rc[10], ru[10], rd[10];
    bool active = (base < PLANE);

    if (active) {
        const float* plane = hm + (size_t)b * PLANE;
        int hw = base % HWSZ;
        int h  = hw / WW;
        int w  = hw % WW;
        const float* p = plane + base;
        const float NEG = -3.4e38f;

        {
            float4 a = *reinterpret_cast<const float4*>(p);
            float4 c = *reinterpret_cast<const float4*>(p + 4);
            rc[1]=a.x; rc[2]=a.y; rc[3]=a.z; rc[4]=a.w;
            rc[5]=c.x; rc[6]=c.y; rc[7]=c.z; rc[8]=c.w;
            rc[0] = (w > 0)      ? p[-1] : NEG;
            rc[9] = (w + 8 < WW) ? p[8]  : NEG;
        }
        if (h > 0) {
            const float* q = p - WW;
            float4 a = *reinterpret_cast<const float4*>(q);
            float4 c = *reinterpret_cast<const float4*>(q + 4);
            ru[1]=a.x; ru[2]=a.y; ru[3]=a.z; ru[4]=a.w;
            ru[5]=c.x; ru[6]=c.y; ru[7]=c.z; ru[8]=c.w;
            ru[0] = (w > 0)      ? q[-1] : NEG;
            ru[9] = (w + 8 < WW) ? q[8]  : NEG;
        } else {
            #pragma unroll
            for (int j = 0; j < 10; j++) ru[j] = NEG;
        }
        if (h + 1 < HH) {
            const float* q = p + WW;
            float4 a = *reinterpret_cast<const float4*>(q);
            float4 c = *reinterpret_cast<const float4*>(q + 4);
            rd[1]=a.x; rd[2]=a.y; rd[3]=a.z; rd[4]=a.w;
            rd[5]=c.x; rd[6]=c.y; rd[7]=c.z; rd[8]=c.w;
            rd[0] = (w > 0)      ? q[-1] : NEG;
            rd[9] = (w + 8 < WW) ? q[8]  : NEG;
        } else {
            #pragma unroll
            for (int j = 0; j < 10; j++) rd[j] = NEG;
        }
    }

    #pragma unroll
    for (int j = 0; j < 8; j++) {
        bool hi = false;
        unsigned long long key = 0;
        if (active) {
            float v = rc[j + 1];
            float m = fmaxf(rc[j], rc[j + 2]);
            m = fmaxf(m, fmaxf(fmaxf(ru[j], ru[j + 1]), ru[j + 2]));
            m = fmaxf(m, fmaxf(fmaxf(rd[j], rd[j + 1]), rd[j + 2]));
            if (v >= m) {                          // local maximum
                unsigned int ord = ordkey(v);
                atomicAdd(&g_zero[(b * NSH + sh) * NBUCK + (int)(ord >> 19)], 1);
                if (v >= CUTRAW) {                 // store only high survivors
                    hi = true;
                    unsigned int idx = (unsigned int)(base + j);   // c*HW + hw
                    key = ((unsigned long long)ord << 32) |
                          (unsigned long long)(~idx);
                }
            }
        }
        unsigned mask = __ballot_sync(0xFFFFFFFFu, hi);
        if (mask) {
            int leader = __ffs(mask) - 1;
            int wbase = 0;
            if (lane == leader) wbase = atomicAdd(&s_cnt, __popc(mask));
            wbase = __shfl_sync(0xFFFFFFFFu, wbase, leader);
            if (hi) {
                int pos = wbase + __popc(mask & ((1u << lane) - 1));
                if (pos < SKEYS) s_keys[pos] = key;
            }
        }
    }

    __syncthreads();
    if (s_cnt == 0) return;
    if (threadIdx.x == 0)
        s_base = atomicAdd(&g_zero[SCOUNT_OFF + b], s_cnt);
    __syncthreads();

    int nblk  = (s_cnt < SKEYS) ? s_cnt : SKEYS;
    int gbase = s_base;
    for (int i = threadIdx.x; i < nblk; i += 256) {
        int pp = gbase + i;
        if (pp < HICAP) g_surv[b * HICAP + pp] = s_keys[i];
    }
}

// ---------------------------------------------------------------------------
// K2: threshold select (register buckets + warp-shuffle suffix scan) FUSED
//     with candidate collection from the small high-survivor list.
// ---------------------------------------------------------------------------
__global__ __launch_bounds__(1024)
void k2_thresh_collect(int K) {
    int b    = blockIdx.x;
    int t    = threadIdx.x;
    int lane = t & 31;
    int wid  = t >> 5;

    __shared__ int warpsum[32];
    __shared__ int wsuf[32];
    __shared__ int sT, s_cnt;
    if (t == 0) { sT = 0; s_cnt = 0; }

    int bk[8];
    int s = 0;
    #pragma unroll
    for (int j = 0; j < 8; j++) {
        int bkix = t * 8 + j;
        int v = 0;
        #pragma unroll
        for (int sh = 0; sh < NSH; sh++)
            v += g_zero[(b * NSH + sh) * NBUCK + bkix];
        bk[j] = v;
        s += v;
    }

    // within-warp inclusive suffix sum (lane..31)
    int val = s;
    #pragma unroll
    for (int d = 1; d < 32; d <<= 1) {
        int v = __shfl_down_sync(0xFFFFFFFFu, val, d);
        if (lane + d < 32) val += v;
    }
    if (lane == 0) warpsum[wid] = val;
    __syncthreads();

    if (wid == 0) {
        int wv = warpsum[lane];
        #pragma unroll
        for (int d = 1; d < 32; d <<= 1) {
            int v = __shfl_down_sync(0xFFFFFFFFu, wv, d);
            if (lane + d < 32) wv += v;
        }
        wsuf[lane] = wv;     // inclusive suffix over warp totals
    }
    __syncthreads();

    int higher = (wid < 31) ? wsuf[wid + 1] : 0;
    int suf    = val + higher;        // inclusive suffix sum at thread t
    int snext  = suf - s;             // suffix at t+1 boundary

    if (suf >= K && snext < K) {
        int cum = snext;
        int T = t * 8;
        #pragma unroll
        for (int j = 7; j >= 0; j--) {
            cum += bk[j];
            if (cum >= K) { T = t * 8 + j; break; }
        }
        sT = T;
    }
    __syncthreads();

    int T = sT;                        // 0 if fewer than K survivors total
    if (t == 0) g_thresh[b] = T;
    if (T < CUTB) return;              // fallback kernel (k3b) will collect

    // Collect candidates from the high-survivor list (fast path).
    int n_hi = g_zero[SCOUNT_OFF + b];
    if (n_hi > HICAP) n_hi = HICAP;
    for (int i = t; i < n_hi; i += 1024) {
        unsigned long long key = g_surv[b * HICAP + i];
        if ((int)(key >> 51) >= T) {
            int pos = atomicAdd(&s_cnt, 1);
            if (pos < CAP) g_cand[b * CAP + pos] = key;
        }
    }
    __syncthreads();
    if (t == 0) {
        int c = s_cnt;
        g_zero[COUNT_OFF + b] = (c < CAP) ? c : CAP;
    }
}

// ---------------------------------------------------------------------------
// K3b: exact fallback — only runs if the threshold fell below the storage
//      cutoff (never for this input). Rescans hm with scalar NMS and collects
//      every survivor with bucket >= T. Early-exits otherwise.
// ---------------------------------------------------------------------------
__global__ __launch_bounds__(256)
void k3b_fallback(const float* __restrict__ hm) {
    int b = blockIdx.y;
    int T = g_thresh[b];
    if (T >= CUTB) return;             // fast path handled it

    const float* plane = hm + (size_t)b * PLANE;
    for (int i = blockIdx.x * 256 + threadIdx.x; i < PLANE; i += K4_BLK * 256) {
        int hw = i % HWSZ;
        int h  = hw / WW;
        int w  = hw % WW;
        float v = plane[i];
        bool keep = true;
        for (int dh = -1; dh <= 1; dh++) {
            int hh = h + dh;
            if (hh < 0 || hh >= HH) continue;
            for (int dw = -1; dw <= 1; dw++) {
                if (dh == 0 && dw == 0) continue;
                int ww = w + dw;
                if (ww < 0 || ww >= WW) continue;
                if (plane[i + dh * WW + dw] > v) { keep = false; }
            }
        }
        if (keep) {
            unsigned int ord = ordkey(v);
            if ((int)(ord >> 19) >= T) {
                int pos = atomicAdd(&g_zero[COUNT_OFF + b], 1);
                if (pos < CAP) {
                    unsigned int idx = (unsigned int)i;
                    g_cand[b * CAP + pos] =
                        ((unsigned long long)ord << 32) |
                        (unsigned long long)(~idx);
                }
            }
        }
    }
}

// ---------------------------------------------------------------------------
// K4: warp-per-candidate rank selection with candidate-stride loop.
// ---------------------------------------------------------------------------
__global__ __launch_bounds__(256)
void k4_rank_gather(const float* __restrict__ cen_offset,
                    const float* __restrict__ direction,
                    const float* __restrict__ z_coor,
                    const float* __restrict__ dimf,
                    float* __restrict__ out,
                    int K) {
    int b    = blockIdx.y;
    int lane = threadIdx.x & 31;
    int warp = threadIdx.x >> 5;
    int n    = g_zero[COUNT_OFF + b];
    if (n > CAP) n = CAP;

    const unsigned long long* cp = &g_cand[b * CAP];
    const float* off = cen_offset + (size_t)b * 2 * HWSZ;
    const float* dir = direction  + (size_t)b * 2 * HWSZ;
    const float* zc  = z_coor     + (size_t)b * 1 * HWSZ;
    const float* dm  = dimf       + (size_t)b * 3 * HWSZ;

    for (int cand = blockIdx.x * 8 + warp; cand < n; cand += K4_BLK * 8) {
        unsigned long long key = cp[cand];

        int rank = 0;
        for (int j = lane; j < n; j += 32)
            rank += (cp[j] > key);
        rank = __reduce_add_sync(0xFFFFFFFFu, rank);
        if (rank >= K) continue;

        if (lane == 0) {
            unsigned int ord  = (unsigned int)(key >> 32);
            unsigned int bits = (ord & 0x80000000u) ? (ord ^ 0x80000000u) : ~ord;
            float score = sigclip(__uint_as_float(bits));
            unsigned int idx = ~((unsigned int)key);       // c*HW + hw
            int c  = (int)(idx / HWSZ);
            int hw = (int)(idx - (unsigned int)c * HWSZ);
            int r  = hw / WW;
            int w  = hw - r * WW;

            float* o = out + ((size_t)b * K + rank) * 10;
            o[0] = score;
            o[1] = (float)w + sigclip(off[hw]);
            o[2] = (float)r + sigclip(off[HWSZ + hw]);
            o[3] = zc[hw];
            o[4] = dm[hw];
            o[5] = dm[HWSZ + hw];
            o[6] = dm[2 * HWSZ + hw];
            o[7] = dir[hw];
            o[8] = dir[HWSZ + hw];
            o[9] = (float)c;
        }
    }
}

// ---------------------------------------------------------------------------
// Host launcher — kernel nodes only.
// ---------------------------------------------------------------------------
extern "C" void kernel_launch(void* const* d_in, const int* in_sizes, int n_in,
                              void* d_out, int out_size) {
    const float* hm   = (const float*)d_in[0];
    const float* off  = (const float*)d_in[1];
    const float* dir  = (const float*)d_in[2];
    const float* zc   = (const float*)d_in[3];
    const float* dm   = (const float*)d_in[4];
    float* out = (float*)d_out;

    int B = in_sizes[0] / PLANE;
    if (B < 1) B = 1;
    if (B > MAXB) B = MAXB;
    int K = out_size / (B * 10);
    if (K < 1) K = 1;

    int ztotal = ZERO_INTS + out_size;
    k0_zero<<<(ztotal + 1023) / 1024, 1024>>>(out, out_size);
    k1_nms<<<dim3(K1_BLOCKS, B), 256>>>(hm);
    k2_thresh_collect<<<B, 1024>>>(K);
    k3b_fallback<<<dim3(K4_BLK, B), 256>>>(hm);
    k4_rank_gather<<<dim3(K4_BLK, B), 256>>>(off, dir, zc, dm, out, K);
}